// round 3
// baseline (speedup 1.0000x reference)
#include <cuda_runtime.h>
#include <cfloat>

// ---------------------------------------------------------------------------
// VectorQuantizer (VQ-VAE) fused pipeline, sm_100a
//   (Round-2 resubmit: Round-1 kernel was never run — broker container
//    failed twice. Identical source so the Round-1 prediction gets measured.)
//
//   inputs:  z[32,1024,64] f32, embedding[4096,64] f32,
//            ema_cluster_size[4096] f32, ema_w[4096,64] f32
//   outputs (concat, f32): z_q_st (2097152), indices (32768), loss (1),
//            new_embedding (262144), new_cluster_size (4096), new_ema_w (262144)
//
// Argmin emulates the reference's rounding:
//   v = fsub_rn( fadd_rn(||z||^2, ||e||^2), 2*(z.e) ),  dot = sequential fp32
//   FMA over d=0..63; ties resolved to lowest index (jnp.argmin semantics).
// ---------------------------------------------------------------------------

#define NROWS 32768
#define KN    4096
#define DIM   64
#define BM    64          // rows per block
#define BN    128         // codes per k-chunk
#define NCHUNK (KN / BN)  // 32
#define NBLK   (NROWS / BM) // 512

// output offsets (elements)
#define O_ZQ   0
#define O_IND  2097152
#define O_LOSS 2129920
#define O_NE   2129921
#define O_NCS  2392065
#define O_NW   2396161

// scratch (no allocations allowed -> __device__ globals)
__device__ int   g_idx[NROWS];
__device__ float g_zz[NROWS];
__device__ float g_e2[KN];
__device__ float g_counts[KN];
__device__ float g_dw[KN * DIM];
__device__ float g_cs[KN];
__device__ float g_losssum;

// ---- packed f32x2 helpers (Blackwell) ----
__device__ __forceinline__ unsigned long long pk2(float x, float y) {
    unsigned long long r;
    asm("mov.b64 %0, {%1, %2};" : "=l"(r) : "f"(x), "f"(y));
    return r;
}
__device__ __forceinline__ unsigned long long ffma2(unsigned long long a,
                                                    unsigned long long b,
                                                    unsigned long long c) {
    unsigned long long d;
    asm("fma.rn.f32x2 %0, %1, %2, %3;" : "=l"(d) : "l"(a), "l"(b), "l"(c));
    return d;
}
__device__ __forceinline__ void upk2(unsigned long long v, float& x, float& y) {
    asm("mov.b64 {%0, %1}, %2;" : "=f"(x), "=f"(y) : "l"(v));
}

// ---------------------------------------------------------------------------
// K0: zero scratch + ||e_k||^2 + ||z_n||^2 (rounded squares, sequential sum
// to mirror XLA's mul-then-reduce; order effects are sub-ulp-irrelevant)
// ---------------------------------------------------------------------------
__global__ void k_prep(const float* __restrict__ z, const float* __restrict__ emb) {
    int i = blockIdx.x * blockDim.x + threadIdx.x;   // 65536 threads
    int stride = gridDim.x * blockDim.x;
    for (int j = i; j < KN * DIM; j += stride) g_dw[j] = 0.f;
    if (i < KN) {
        g_counts[i] = 0.f;
        const float* e = emb + (size_t)i * DIM;
        float s = 0.f;
        #pragma unroll
        for (int d = 0; d < DIM; d++) {
            float v = __ldg(e + d);
            s = __fadd_rn(s, __fmul_rn(v, v));
        }
        g_e2[i] = s;
    }
    if (i < NROWS) {
        const float* zr = z + (size_t)i * DIM;
        float s = 0.f;
        #pragma unroll
        for (int d = 0; d < DIM; d++) {
            float v = __ldg(zr + d);
            s = __fadd_rn(s, __fmul_rn(v, v));
        }
        g_zz[i] = s;
    }
    if (i == 0) g_losssum = 0.f;
}

// ---------------------------------------------------------------------------
// K1: argmin_k fsub_rn(fadd_rn(zz, ee_k), 2 z.e_k) — fp32 packed f32x2 FMA
// block: 256 threads, tile BM=64 rows x BN=128 codes, full D=64 slab in smem.
// thread (tx,ty): tx in [0,16) -> 8 codes, ty in [0,16) -> 4 rows.
// smem transposed [d][.] with XOR-((d>>2)&mask) float4-group swizzle.
// ---------------------------------------------------------------------------
__global__ void __launch_bounds__(256, 2) k_argmin(
    const float* __restrict__ z, const float* __restrict__ emb,
    float* __restrict__ out)
{
    __shared__ float zs[DIM * BM];   // 16 KB
    __shared__ float es[DIM * BN];   // 32 KB

    const int tid = threadIdx.x;
    const int tx  = tid & 15;
    const int ty  = tid >> 4;
    const int r0  = blockIdx.x * BM;

    // ---- fill zs: transposed + swizzled ----
    const float4* z4 = (const float4*)z + (size_t)r0 * (DIM / 4);
    for (int i = tid; i < BM * (DIM / 4); i += 256) {
        int r  = i >> 4;      // 0..63
        int d4 = i & 15;      // 0..15
        float4 v = z4[r * (DIM / 4) + d4];
        int rq = r >> 2, rl = r & 3;
        int col = (((rq ^ d4) & 15) << 2) + rl;
        zs[(d4 * 4 + 0) * BM + col] = v.x;
        zs[(d4 * 4 + 1) * BM + col] = v.y;
        zs[(d4 * 4 + 2) * BM + col] = v.z;
        zs[(d4 * 4 + 3) * BM + col] = v.w;
    }

    // per-thread rows' ||z||^2
    float zzr[4];
    #pragma unroll
    for (int rr = 0; rr < 4; rr++) zzr[rr] = __ldg(&g_zz[r0 + ty * 4 + rr]);

    float minv[4] = {FLT_MAX, FLT_MAX, FLT_MAX, FLT_MAX};
    int   mini[4] = {0, 0, 0, 0};

    const float4* e4 = (const float4*)emb;

    for (int kc = 0; kc < NCHUNK; kc++) {
        const int k0 = kc * BN;
        __syncthreads();   // protect es (and first-iter zs) from prior readers
        // ---- fill es: transposed + swizzled ----
        for (int i = tid; i < BN * (DIM / 4); i += 256) {   // 2048 -> 8 iters
            int kk = i >> 4;   // 0..127
            int d4 = i & 15;
            float4 v = e4[(size_t)(k0 + kk) * (DIM / 4) + d4];
            int kq = kk >> 2, kl = kk & 3;
            int col = (((kq ^ d4) & 31) << 2) + kl;
            es[(d4 * 4 + 0) * BN + col] = v.x;
            es[(d4 * 4 + 1) * BN + col] = v.y;
            es[(d4 * 4 + 2) * BN + col] = v.z;
            es[(d4 * 4 + 3) * BN + col] = v.w;
        }
        __syncthreads();

        unsigned long long acc[2][8];
        #pragma unroll
        for (int a = 0; a < 2; a++)
            #pragma unroll
            for (int b = 0; b < 8; b++) acc[a][b] = 0ull;

        // sequential FMA chain over d=0..63 per output element (per f32x2
        // lane) — accumulation order matches the reference's depth loop
        #pragma unroll 8
        for (int d = 0; d < DIM; d++) {
            int sw = (d >> 2) & 15;
            float4 av = *(const float4*)(zs + d * BM + (((ty ^ sw) & 15) << 2));
            float4 b0 = *(const float4*)(es + d * BN + ((((2 * tx)     ^ sw) & 31) << 2));
            float4 b1 = *(const float4*)(es + d * BN + ((((2 * tx + 1) ^ sw) & 31) << 2));
            unsigned long long A0 = pk2(av.x, av.y);   // rows rb+0, rb+1
            unsigned long long A1 = pk2(av.z, av.w);   // rows rb+2, rb+3
            unsigned long long B[8] = {
                pk2(b0.x, b0.x), pk2(b0.y, b0.y), pk2(b0.z, b0.z), pk2(b0.w, b0.w),
                pk2(b1.x, b1.x), pk2(b1.y, b1.y), pk2(b1.z, b1.z), pk2(b1.w, b1.w)
            };
            #pragma unroll
            for (int b = 0; b < 8; b++) {
                acc[0][b] = ffma2(A0, B[b], acc[0][b]);
                acc[1][b] = ffma2(A1, B[b], acc[1][b]);
            }
        }

        // ---- epilogue: v = fsub_rn(fadd_rn(zz, ee), 2*dot); ties -> lowest k
        #pragma unroll
        for (int b = 0; b < 8; b++) {
            int kg = k0 + tx * 8 + b;
            float e2v = __ldg(&g_e2[kg]);
            float x0, x1, x2, x3;
            upk2(acc[0][b], x0, x1);
            upk2(acc[1][b], x2, x3);
            float v;
            v = __fsub_rn(__fadd_rn(zzr[0], e2v), 2.f * x0);
            if (v < minv[0]) { minv[0] = v; mini[0] = kg; }
            v = __fsub_rn(__fadd_rn(zzr[1], e2v), 2.f * x1);
            if (v < minv[1]) { minv[1] = v; mini[1] = kg; }
            v = __fsub_rn(__fadd_rn(zzr[2], e2v), 2.f * x2);
            if (v < minv[2]) { minv[2] = v; mini[2] = kg; }
            v = __fsub_rn(__fadd_rn(zzr[3], e2v), 2.f * x3);
            if (v < minv[3]) { minv[3] = v; mini[3] = kg; }
        }
    }

    // ---- cross-tx reduction (16 candidates per row) ----
    __syncthreads();
    float* redv = zs;                    // reuse: 64*16 floats
    int*   redi = (int*)(zs + BM * 16);
    #pragma unroll
    for (int rr = 0; rr < 4; rr++) {
        redv[(ty * 4 + rr) * 16 + tx] = minv[rr];
        redi[(ty * 4 + rr) * 16 + tx] = mini[rr];
    }
    __syncthreads();
    if (tid < BM) {
        float bv = FLT_MAX; int bi = 0x7fffffff;
        #pragma unroll
        for (int t = 0; t < 16; t++) {
            float v = redv[tid * 16 + t];
            int   i = redi[tid * 16 + t];
            if (v < bv || (v == bv && i < bi)) { bv = v; bi = i; }
        }
        g_idx[r0 + tid] = bi;
        out[O_IND + r0 + tid] = (float)bi;
    }
}

// ---------------------------------------------------------------------------
// K2: gather z_q, straight-through output, loss partial, scatter counts/dw
// warp per row (32768 warps)
// ---------------------------------------------------------------------------
__global__ void k_scatter(const float* __restrict__ z, const float* __restrict__ emb,
                          float* __restrict__ out)
{
    int row = blockIdx.x * 8 + (threadIdx.x >> 5);
    int ln  = threadIdx.x & 31;
    int idx = g_idx[row];
    const float* zr = z   + (size_t)row * DIM;
    const float* er = emb + (size_t)idx * DIM;
    float* zq = out + O_ZQ + (size_t)row * DIM;
    float l = 0.f;
    #pragma unroll
    for (int t = 0; t < 2; t++) {
        int j = ln + 32 * t;
        float zv = zr[j], ev = __ldg(er + j);
        // straight-through: z + (z_q - z), forced rounding to match reference
        zq[j] = __fadd_rn(zv, __fsub_rn(ev, zv));
        float dd = __fsub_rn(zv, ev);
        l += dd * dd;
        atomicAdd(&g_dw[idx * DIM + j], zv);
    }
    if (ln == 0) atomicAdd(&g_counts[idx], 1.f);
    #pragma unroll
    for (int o = 16; o; o >>= 1) l += __shfl_xor_sync(0xffffffffu, l, o);
    __shared__ float sl[8];
    if (ln == 0) sl[threadIdx.x >> 5] = l;
    __syncthreads();
    if (threadIdx.x == 0) {
        float s = 0.f;
        #pragma unroll
        for (int w = 0; w < 8; w++) s += sl[w];
        atomicAdd(&g_losssum, s);
    }
}

// ---------------------------------------------------------------------------
// K3: new_cluster_size, n, normalized cluster size, loss  (single block)
// ---------------------------------------------------------------------------
__global__ void k_fin1(const float* __restrict__ ema_cs, float* __restrict__ out)
{
    int tid = threadIdx.x;  // 1024
    float ncs[4];
    float s = 0.f;
    #pragma unroll
    for (int j = 0; j < 4; j++) {
        int k = tid + j * 1024;
        float v = 0.99f * ema_cs[k] + 0.01f * g_counts[k];
        ncs[j] = v; s += v;
        out[O_NCS + k] = v;
    }
    __shared__ float sp[32];
    #pragma unroll
    for (int o = 16; o; o >>= 1) s += __shfl_xor_sync(0xffffffffu, s, o);
    if ((tid & 31) == 0) sp[tid >> 5] = s;
    __syncthreads();
    if (tid < 32) {
        float v = sp[tid];
        #pragma unroll
        for (int o = 16; o; o >>= 1) v += __shfl_xor_sync(0xffffffffu, v, o);
        if (tid == 0) sp[0] = v;
    }
    __syncthreads();
    float n = sp[0];
    float denom = n + (float)KN * 1e-5f;
    #pragma unroll
    for (int j = 0; j < 4; j++) {
        int k = tid + j * 1024;
        g_cs[k] = (ncs[j] + 1e-5f) / denom * n;
    }
    if (tid == 0) out[O_LOSS] = 0.25f * (g_losssum / 2097152.0f);
}

// ---------------------------------------------------------------------------
// K4: new_ema_w and new_embedding
// ---------------------------------------------------------------------------
__global__ void k_fin2(const float* __restrict__ ema_w, float* __restrict__ out)
{
    int i = blockIdx.x * blockDim.x + threadIdx.x;   // 262144 total
    float nw = 0.99f * ema_w[i] + 0.01f * g_dw[i];
    out[O_NW + i] = nw;
    out[O_NE + i] = __fdiv_rn(nw, g_cs[i >> 6]);
}

// ---------------------------------------------------------------------------
extern "C" void kernel_launch(void* const* d_in, const int* in_sizes, int n_in,
                              void* d_out, int out_size)
{
    const float* z      = (const float*)d_in[0];
    const float* emb    = (const float*)d_in[1];
    const float* ema_cs = (const float*)d_in[2];
    const float* ema_w  = (const float*)d_in[3];
    float* out = (float*)d_out;

    k_prep   <<<256, 256>>>(z, emb);
    k_argmin <<<NBLK, 256>>>(z, emb, out);
    k_scatter<<<NROWS / 8, 256>>>(z, emb, out);
    k_fin1   <<<1, 1024>>>(ema_cs, out);
    k_fin2   <<<KN * DIM / 256, 256>>>(ema_w, out);
}

// round 4
// speedup vs baseline: 1.3961x; 1.3961x over previous
#include <cuda_runtime.h>
#include <cfloat>

// ---------------------------------------------------------------------------
// VectorQuantizer (VQ-VAE) fused pipeline, sm_100a
//   R3 -> R4: k_argmin restructured so BOTH f32x2 operands are loaded from
//   smem directly as aligned 64-bit register pairs (zero mov.b64 packs).
//   Lanes own code-pairs (distinct LDS.128, XOR-swizzled transposed tile);
//   rows are the broadcast operand, staged pre-duplicated. Numerics identical
//   to the R3 passing kernel (sequential fp32 FMA chain per (row,code),
//   v = fsub_rn(fadd_rn(zz,ee), 2*dot), ties -> lowest index).
// ---------------------------------------------------------------------------

#define NROWS 32768
#define KN    4096
#define DIM   64
#define BM    64            // rows per block (8 warps x 8 rows)
#define CPC   256           // codes per chunk
#define NCH   (KN / CPC)    // 16
#define NBLK  (NROWS / BM)  // 512

// output offsets (elements)
#define O_ZQ   0
#define O_IND  2097152
#define O_LOSS 2129920
#define O_NE   2129921
#define O_NCS  2392065
#define O_NW   2396161

// dynamic smem layout (floats)
#define SM_ES  0                    // [64][256]  es transposed+swizzled
#define SM_ZD  (64 * 256)           // [64][128]  z rows duplicated
#define SM_ZZ  (SM_ZD + 64 * 128)   // [64]       ||z||^2 per block row
#define SM_TOT_F (SM_ZZ + 64)
#define SM_BYTES (SM_TOT_F * 4)     // 98560 B

// scratch (no allocations allowed -> __device__ globals)
__device__ int   g_idx[NROWS];
__device__ float g_zz[NROWS];
__device__ float g_e2[KN];
__device__ float g_counts[KN];
__device__ float g_dw[KN * DIM];
__device__ float g_cs[KN];
__device__ float g_losssum;

// ---- packed f32x2 helpers (Blackwell) ----
__device__ __forceinline__ unsigned long long ffma2(unsigned long long a,
                                                    unsigned long long b,
                                                    unsigned long long c) {
    unsigned long long d;
    asm("fma.rn.f32x2 %0, %1, %2, %3;" : "=l"(d) : "l"(a), "l"(b), "l"(c));
    return d;
}
__device__ __forceinline__ void upk2(unsigned long long v, float& x, float& y) {
    asm("mov.b64 {%0, %1}, %2;" : "=f"(x), "=f"(y) : "l"(v));
}

// ---------------------------------------------------------------------------
// K0: zero scratch + ||e_k||^2 + ||z_n||^2 (sequential rounded sums -- DO NOT
// change: this reproduces the reference's distance grid; verified rel_err
// 4.8e-7 in R3)
// ---------------------------------------------------------------------------
__global__ void k_prep(const float* __restrict__ z, const float* __restrict__ emb) {
    int i = blockIdx.x * blockDim.x + threadIdx.x;   // 65536 threads
    int stride = gridDim.x * blockDim.x;
    for (int j = i; j < KN * DIM; j += stride) g_dw[j] = 0.f;
    if (i < KN) {
        g_counts[i] = 0.f;
        const float* e = emb + (size_t)i * DIM;
        float s = 0.f;
        #pragma unroll
        for (int d = 0; d < DIM; d++) {
            float v = __ldg(e + d);
            s = __fadd_rn(s, __fmul_rn(v, v));
        }
        g_e2[i] = s;
    }
    if (i < NROWS) {
        const float* zr = z + (size_t)i * DIM;
        float s = 0.f;
        #pragma unroll
        for (int d = 0; d < DIM; d++) {
            float v = __ldg(zr + d);
            s = __fadd_rn(s, __fmul_rn(v, v));
        }
        g_zz[i] = s;
    }
    if (i == 0) g_losssum = 0.f;
}

// ---------------------------------------------------------------------------
// K1: argmin. 256 threads, 8 warps x 8 rows; warp covers 256 codes/chunk
// (lane = 8 codes as 4 f32x2 pairs). Per d-step per thread:
//   2x LDS.128 (codes, distinct, swizzled conflict-free)
//   4x LDS.128 (rows, broadcast, pre-duplicated)
//   32x fma.rn.f32x2
// ---------------------------------------------------------------------------
__global__ void __launch_bounds__(256, 2) k_argmin(
    const float* __restrict__ z, const float* __restrict__ emb,
    float* __restrict__ out)
{
    extern __shared__ float sm[];
    float* es  = sm + SM_ES;
    float* zd  = sm + SM_ZD;
    float* zzs = sm + SM_ZZ;

    const int tid = threadIdx.x;
    const int ln  = tid & 31;
    const int w   = tid >> 5;
    const int r0  = blockIdx.x * BM;

    // ---- stage z duplicated: [d][2r]=[d][2r+1]=z[r0+r][d] (one-time; the
    // 16-way-conflicted transpose writes are ~0.5% of block time) ----
    const float4* z4 = (const float4*)z;
    #pragma unroll
    for (int it = 0; it < 4; it++) {
        int i  = tid + it * 256;        // 1024 items
        int r  = i >> 4;                // 0..63
        int d4 = i & 15;                // 0..15
        float4 v = z4[(size_t)(r0 + r) * 16 + d4];
        *(float2*)(zd + (4 * d4 + 0) * 128 + 2 * r) = make_float2(v.x, v.x);
        *(float2*)(zd + (4 * d4 + 1) * 128 + 2 * r) = make_float2(v.y, v.y);
        *(float2*)(zd + (4 * d4 + 2) * 128 + 2 * r) = make_float2(v.z, v.z);
        *(float2*)(zd + (4 * d4 + 3) * 128 + 2 * r) = make_float2(v.w, v.w);
    }
    if (tid < BM) zzs[tid] = __ldg(&g_zz[r0 + tid]);

    float minv[8];
    int   mini[8];
    #pragma unroll
    for (int r = 0; r < 8; r++) { minv[r] = FLT_MAX; mini[r] = 0; }

    const float4* e4 = (const float4*)emb;
    const int cb = 4 * ln;   // lane's code offset within chunk (group ln)

    for (int ch = 0; ch < NCH; ch++) {
        const int k0 = ch * CPC;
        __syncthreads();   // prior chunk's readers done (also covers zd 1st iter)
        // ---- stage es transposed [d][code] with XOR-group swizzle:
        // code k (group g=k>>2) at depth d stored at col ((g ^ (d>>2)) * 4 + (k&3))
        #pragma unroll
        for (int it = 0; it < 16; it++) {
            int i  = tid + it * 256;    // 4096 items
            int k  = i >> 4;            // 0..255
            int d4 = i & 15;
            float4 v = e4[(size_t)(k0 + k) * 16 + d4];
            int g = k >> 2, kl = k & 3;
            int col = ((g ^ d4) & 63) * 4 + kl;
            es[(4 * d4 + 0) * 256 + col] = v.x;
            es[(4 * d4 + 1) * 256 + col] = v.y;
            es[(4 * d4 + 2) * 256 + col] = v.z;
            es[(4 * d4 + 3) * 256 + col] = v.w;
        }
        __syncthreads();

        // prefetch ||e||^2 for this lane's 8 codes (latency hidden by d-loop)
        float e2v[8];
        #pragma unroll
        for (int j = 0; j < 4; j++) {
            e2v[j]     = __ldg(&g_e2[k0 + cb + j]);
            e2v[4 + j] = __ldg(&g_e2[k0 + 128 + cb + j]);
        }

        unsigned long long acc[8][4];
        #pragma unroll
        for (int r = 0; r < 8; r++)
            #pragma unroll
            for (int p = 0; p < 4; p++) acc[r][p] = 0ull;

        // ---- main d loop: sequential fp32 FMA chain per (row, code) ----
        #pragma unroll 1
        for (int d4i = 0; d4i < 16; d4i++) {
            const int slotf = ((ln ^ d4i) & 63) * 4;   // lane's group ln after swizzle
            const float* eb = es + d4i * 4 * 256;
            const float* zb = zd + d4i * 4 * 128 + w * 16;
            #pragma unroll
            for (int c = 0; c < 4; c++) {
                const float* er = eb + c * 256;
                // codes 4ln..4ln+3 and 128+4ln..+3 as 4 aligned f32x2 pairs
                ulonglong2 Ca = *(const ulonglong2*)(er + slotf);
                ulonglong2 Cb = *(const ulonglong2*)(er + 128 + slotf);
                const ulonglong2* zr2 = (const ulonglong2*)(zb + c * 128);
                ulonglong2 R01 = zr2[0];   // rows 8w+0, 8w+1 (dup pairs)
                ulonglong2 R23 = zr2[1];
                ulonglong2 R45 = zr2[2];
                ulonglong2 R67 = zr2[3];
                #define FMAROW(r, Rv) \
                    acc[r][0] = ffma2(Ca.x, Rv, acc[r][0]); \
                    acc[r][1] = ffma2(Ca.y, Rv, acc[r][1]); \
                    acc[r][2] = ffma2(Cb.x, Rv, acc[r][2]); \
                    acc[r][3] = ffma2(Cb.y, Rv, acc[r][3]);
                FMAROW(0, R01.x) FMAROW(1, R01.y)
                FMAROW(2, R23.x) FMAROW(3, R23.y)
                FMAROW(4, R45.x) FMAROW(5, R45.y)
                FMAROW(6, R67.x) FMAROW(7, R67.y)
                #undef FMAROW
            }
        }

        // ---- epilogue: v = fsub_rn(fadd_rn(zz, ee), 2*dot); ascending code
        // order within thread; strict < keeps lowest index ----
        #pragma unroll
        for (int r = 0; r < 8; r++) {
            float zz = zzs[w * 8 + r];
            #pragma unroll
            for (int p = 0; p < 4; p++) {
                float x0, x1;
                upk2(acc[r][p], x0, x1);
                int kg = k0 + cb + 2 * p + (p >= 2 ? 124 : 0); // p2->+128, p3->+130
                float v0 = __fsub_rn(__fadd_rn(zz, e2v[2 * p]),
                                     __fmul_rn(2.f, x0));
                if (v0 < minv[r]) { minv[r] = v0; mini[r] = kg; }
                float v1 = __fsub_rn(__fadd_rn(zz, e2v[2 * p + 1]),
                                     __fmul_rn(2.f, x1));
                if (v1 < minv[r]) { minv[r] = v1; mini[r] = kg + 1; }
            }
        }
    }

    // ---- warp-wide argmin per row (warps own disjoint rows) ----
    #pragma unroll
    for (int r = 0; r < 8; r++) {
        float v = minv[r];
        int   i = mini[r];
        #pragma unroll
        for (int off = 16; off; off >>= 1) {
            float ov = __shfl_xor_sync(0xffffffffu, v, off);
            int   oi = __shfl_xor_sync(0xffffffffu, i, off);
            if (ov < v || (ov == v && oi < i)) { v = ov; i = oi; }
        }
        if (ln == 0) {
            int row = r0 + w * 8 + r;
            g_idx[row] = i;
            out[O_IND + row] = (float)i;
        }
    }
}

// ---------------------------------------------------------------------------
// K2: gather z_q, straight-through output, loss partial, scatter counts/dw
// ---------------------------------------------------------------------------
__global__ void k_scatter(const float* __restrict__ z, const float* __restrict__ emb,
                          float* __restrict__ out)
{
    int row = blockIdx.x * 8 + (threadIdx.x >> 5);
    int ln  = threadIdx.x & 31;
    int idx = g_idx[row];
    const float* zr = z   + (size_t)row * DIM;
    const float* er = emb + (size_t)idx * DIM;
    float* zq = out + O_ZQ + (size_t)row * DIM;
    float l = 0.f;
    #pragma unroll
    for (int t = 0; t < 2; t++) {
        int j = ln + 32 * t;
        float zv = zr[j], ev = __ldg(er + j);
        zq[j] = __fadd_rn(zv, __fsub_rn(ev, zv));
        float dd = __fsub_rn(zv, ev);
        l += dd * dd;
        atomicAdd(&g_dw[idx * DIM + j], zv);
    }
    if (ln == 0) atomicAdd(&g_counts[idx], 1.f);
    #pragma unroll
    for (int o = 16; o; o >>= 1) l += __shfl_xor_sync(0xffffffffu, l, o);
    __shared__ float sl[8];
    if (ln == 0) sl[threadIdx.x >> 5] = l;
    __syncthreads();
    if (threadIdx.x == 0) {
        float s = 0.f;
        #pragma unroll
        for (int w = 0; w < 8; w++) s += sl[w];
        atomicAdd(&g_losssum, s);
    }
}

// ---------------------------------------------------------------------------
// K3: new_cluster_size, n, normalized cluster size, loss  (single block)
// ---------------------------------------------------------------------------
__global__ void k_fin1(const float* __restrict__ ema_cs, float* __restrict__ out)
{
    int tid = threadIdx.x;  // 1024
    float ncs[4];
    float s = 0.f;
    #pragma unroll
    for (int j = 0; j < 4; j++) {
        int k = tid + j * 1024;
        float v = 0.99f * ema_cs[k] + 0.01f * g_counts[k];
        ncs[j] = v; s += v;
        out[O_NCS + k] = v;
    }
    __shared__ float sp[32];
    #pragma unroll
    for (int o = 16; o; o >>= 1) s += __shfl_xor_sync(0xffffffffu, s, o);
    if ((tid & 31) == 0) sp[tid >> 5] = s;
    __syncthreads();
    if (tid < 32) {
        float v = sp[tid];
        #pragma unroll
        for (int o = 16; o; o >>= 1) v += __shfl_xor_sync(0xffffffffu, v, o);
        if (tid == 0) sp[0] = v;
    }
    __syncthreads();
    float n = sp[0];
    float denom = n + (float)KN * 1e-5f;
    #pragma unroll
    for (int j = 0; j < 4; j++) {
        int k = tid + j * 1024;
        g_cs[k] = (ncs[j] + 1e-5f) / denom * n;
    }
    if (tid == 0) out[O_LOSS] = 0.25f * (g_losssum / 2097152.0f);
}

// ---------------------------------------------------------------------------
// K4: new_ema_w and new_embedding
// ---------------------------------------------------------------------------
__global__ void k_fin2(const float* __restrict__ ema_w, float* __restrict__ out)
{
    int i = blockIdx.x * blockDim.x + threadIdx.x;   // 262144 total
    float nw = 0.99f * ema_w[i] + 0.01f * g_dw[i];
    out[O_NW + i] = nw;
    out[O_NE + i] = __fdiv_rn(nw, g_cs[i >> 6]);
}

// ---------------------------------------------------------------------------
extern "C" void kernel_launch(void* const* d_in, const int* in_sizes, int n_in,
                              void* d_out, int out_size)
{
    const float* z      = (const float*)d_in[0];
    const float* emb    = (const float*)d_in[1];
    const float* ema_cs = (const float*)d_in[2];
    const float* ema_w  = (const float*)d_in[3];
    float* out = (float*)d_out;

    // attribute-only (no alloc, no stream work) -- capture-safe, idempotent
    cudaFuncSetAttribute(k_argmin, cudaFuncAttributeMaxDynamicSharedMemorySize,
                         SM_BYTES);

    k_prep   <<<256, 256>>>(z, emb);
    k_argmin <<<NBLK, 256, SM_BYTES>>>(z, emb, out);
    k_scatter<<<NROWS / 8, 256>>>(z, emb, out);
    k_fin1   <<<1, 1024>>>(ema_cs, out);
    k_fin2   <<<KN * DIM / 256, 256>>>(ema_w, out);
}